// round 7
// baseline (speedup 1.0000x reference)
#include <cuda_runtime.h>

#define B_ 16
#define A_ 5
#define C_ 512
#define HW_ 256
#define NC 4
#define CCHUNK 32

// out[(i*B+b)] = local[(i*B+b)] + sum_{j != i, j<n, i<n} warp(local[(j*B+b)], trans[b,i,j])
// warp = bilinear grid_sample chained twice (rotation, then constant translation),
// zero pad, align_corners=False. Geometry channel-invariant -> register tap tables.
// Tiles channel-vectorized float4 ([pixel][4ch]); tileA ping-pong -> 2 barriers per
// chunk; next chunk's global loads prefetched into registers during compute.

__global__ __launch_bounds__(256, 3)
void fuse_kernel(const float* __restrict__ feat,
                 const float* __restrict__ trans,
                 const int* __restrict__ nag,
                 float* __restrict__ out)
{
    __shared__ float4 tileA[2][4][256];   // ping-pong source tiles (4 ch/pixel)
    __shared__ float4 tileR[4][256];      // rotation-sampled intermediates

    const int b  = blockIdx.z;
    const int i  = blockIdx.y;
    const int c0 = blockIdx.x * CCHUNK;
    const int t  = threadIdx.x;
    const int x  = t & 15;
    const int y  = t >> 4;

    const int n = nag[b * A_];            // num_agent_tensor[b, 0]
    const bool active = (i < n) && (n > 1);

    const unsigned base = ((unsigned)(i * B_ + b) * C_ + c0) * HW_;
    const float* __restrict__ local = feat + base;
    float* __restrict__ outp        = out  + base;

    // normalized pixel coords (align_corners=False)
    const float xs = (2.f * (float)x + 1.f) / 16.f - 1.f;
    const float ys = (2.f * (float)y + 1.f) / 16.f - 1.f;

    // Per-neighbor tap metadata (channel-invariant).
    float    wA[4][4], wB[4][4];
    unsigned pA[4], pB[4];                // 4 byte-indices packed per table
    unsigned off[4];                      // global element offset of neighbor block
    bool valid[4];

    #pragma unroll
    for (int jj = 0; jj < 4; jj++) {
        const int j = jj + (jj >= i ? 1 : 0);          // skip j == i
        const bool v = active && (j < n);
        valid[jj] = v;
        off[jj]   = ((unsigned)(j * B_ + b) * C_ + c0) * HW_;
        pA[jj] = 0u; pB[jj] = 0u;
        #pragma unroll
        for (int m = 0; m < 4; m++) { wA[jj][m] = 0.f; wB[jj][m] = 0.f; }
        if (v) {
            const float* T = trans + (((b * A_ + i) * A_ + j) * 16);
            const float t00 = T[0], t01 = T[1], t03 = T[3];
            const float t10 = T[4], t11 = T[5], t13 = T[7];

            // ---- stage 1: rotation grid ----
            const float gx = t00 * xs + t01 * ys;
            const float gy = t10 * xs + t11 * ys;
            const float ix = ((gx + 1.f) * 16.f - 1.f) * 0.5f;
            const float iy = ((gy + 1.f) * 16.f - 1.f) * 0.5f;
            const float x0f = floorf(ix), y0f = floorf(iy);
            const float fx = ix - x0f,  fy = iy - y0f;
            const int x0 = (int)x0f, y0 = (int)y0f;
            #pragma unroll
            for (int m = 0; m < 4; m++) {
                const int dx = m & 1, dy = m >> 1;
                const int xi = x0 + dx, yi = y0 + dy;
                const float w = (dx ? fx : 1.f - fx) * (dy ? fy : 1.f - fy);
                const bool in = (xi >= 0) & (xi < 16) & (yi >= 0) & (yi < 16);
                wA[jj][m] = in ? w : 0.f;
                pA[jj]  |= (unsigned)(in ? (yi * 16 + xi) : 0) << (8 * m);
            }

            // ---- stage 2: translation grid ----
            const float xt = t03 * (1.f / 32.f);      // 4*T03/128
            const float yt = -t13 * (1.f / 32.f);
            const float ix2 = ((xs + xt + 1.f) * 16.f - 1.f) * 0.5f;
            const float iy2 = ((ys + yt + 1.f) * 16.f - 1.f) * 0.5f;
            const float x20f = floorf(ix2), y20f = floorf(iy2);
            const float fx2 = ix2 - x20f,  fy2 = iy2 - y20f;
            const int x20 = (int)x20f, y20 = (int)y20f;
            #pragma unroll
            for (int m = 0; m < 4; m++) {
                const int dx = m & 1, dy = m >> 1;
                const int xi = x20 + dx, yi = y20 + dy;
                const float w = (dx ? fx2 : 1.f - fx2) * (dy ? fy2 : 1.f - fy2);
                const bool in = (xi >= 0) & (xi < 16) & (yi >= 0) & (yi < 16);
                wB[jj][m] = in ? w : 0.f;
                pB[jj]  |= (unsigned)(in ? (yi * 16 + xi) : 0) << (8 * m);
            }
        }
    }

    // ---- prologue: prefetch chunk 0 fills into registers ----
    float4 pre[4];
    #pragma unroll
    for (int jj = 0; jj < 4; jj++) {
        if (valid[jj]) {
            const float* src = feat + off[jj];
            pre[jj].x = src[t];
            pre[jj].y = src[HW_ + t];
            pre[jj].z = src[2 * HW_ + t];
            pre[jj].w = src[3 * HW_ + t];
        }
    }

    int p = 0;
    for (int g = 0; g < CCHUNK; g += NC, p ^= 1) {
        // deposit prefetched fills (STS.128, conflict-free)
        #pragma unroll
        for (int jj = 0; jj < 4; jj++) {
            if (valid[jj]) tileA[p][jj][t] = pre[jj];
        }

        float4 acc;
        acc.x = local[(g + 0) * HW_ + t];
        acc.y = local[(g + 1) * HW_ + t];
        acc.z = local[(g + 2) * HW_ + t];
        acc.w = local[(g + 3) * HW_ + t];

        __syncthreads();                  // (a) tileA[p] visible; tileR WAR from prev chunk

        // prefetch next chunk's fills (latency hidden by stage1+stage2 below)
        if (g + NC < CCHUNK) {
            #pragma unroll
            for (int jj = 0; jj < 4; jj++) {
                if (valid[jj]) {
                    const float* src = feat + off[jj] + (unsigned)(g + NC) * HW_;
                    pre[jj].x = src[t];
                    pre[jj].y = src[HW_ + t];
                    pre[jj].z = src[2 * HW_ + t];
                    pre[jj].w = src[3 * HW_ + t];
                }
            }
        }

        // stage 1: rotation sample -> R tiles (one LDS.128 per tap, 4 channels)
        #pragma unroll
        for (int jj = 0; jj < 4; jj++) {
            if (valid[jj]) {
                const float4 v0 = tileA[p][jj][(pA[jj]      ) & 255];
                const float4 v1 = tileA[p][jj][(pA[jj] >>  8) & 255];
                const float4 v2 = tileA[p][jj][(pA[jj] >> 16) & 255];
                const float4 v3 = tileA[p][jj][(pA[jj] >> 24) & 255];
                const float w0 = wA[jj][0], w1 = wA[jj][1], w2 = wA[jj][2], w3 = wA[jj][3];
                float4 r;
                r.x = w0 * v0.x + w1 * v1.x + w2 * v2.x + w3 * v3.x;
                r.y = w0 * v0.y + w1 * v1.y + w2 * v2.y + w3 * v3.y;
                r.z = w0 * v0.z + w1 * v1.z + w2 * v2.z + w3 * v3.z;
                r.w = w0 * v0.w + w1 * v1.w + w2 * v2.w + w3 * v3.w;
                tileR[jj][t] = r;
            }
        }
        __syncthreads();                  // (b) tileR ready

        // stage 2: translation sample -> accumulate
        #pragma unroll
        for (int jj = 0; jj < 4; jj++) {
            if (valid[jj]) {
                const float4 v0 = tileR[jj][(pB[jj]      ) & 255];
                const float4 v1 = tileR[jj][(pB[jj] >>  8) & 255];
                const float4 v2 = tileR[jj][(pB[jj] >> 16) & 255];
                const float4 v3 = tileR[jj][(pB[jj] >> 24) & 255];
                const float w0 = wB[jj][0], w1 = wB[jj][1], w2 = wB[jj][2], w3 = wB[jj][3];
                acc.x += w0 * v0.x + w1 * v1.x + w2 * v2.x + w3 * v3.x;
                acc.y += w0 * v0.y + w1 * v1.y + w2 * v2.y + w3 * v3.y;
                acc.z += w0 * v0.z + w1 * v1.z + w2 * v2.z + w3 * v3.z;
                acc.w += w0 * v0.w + w1 * v1.w + w2 * v2.w + w3 * v3.w;
            }
        }

        outp[(g + 0) * HW_ + t] = acc.x;
        outp[(g + 1) * HW_ + t] = acc.y;
        outp[(g + 2) * HW_ + t] = acc.z;
        outp[(g + 3) * HW_ + t] = acc.w;
    }
}

extern "C" void kernel_launch(void* const* d_in, const int* in_sizes, int n_in,
                              void* d_out, int out_size)
{
    const float* feat  = (const float*)d_in[0];   // [A*B, C, H, W] f32
    const float* trans = (const float*)d_in[1];   // [B, A, A, 4, 4] f32
    const int*   nag   = (const int*)d_in[2];     // [B, A] int32
    float* out = (float*)d_out;                   // [A*B, C, H, W] f32

    dim3 grid(C_ / CCHUNK, A_, B_);
    fuse_kernel<<<grid, 256>>>(feat, trans, nag, out);
}

// round 9
// speedup vs baseline: 1.1919x; 1.1919x over previous
#include <cuda_runtime.h>

#define B_ 16
#define A_ 5
#define C_ 512
#define HW_ 256
#define NC 8
#define CCHUNK 64
#define SMEM_BYTES (96 * 1024)

// out[(i*B+b)] = local[(i*B+b)] + sum_{j != i, j<n, i<n} warp(local[(j*B+b)], trans[b,i,j])
// warp = bilinear grid_sample chained twice (rotation, then constant translation),
// zero pad, align_corners=False. Geometry channel-invariant -> register tap tables.
// Tiles channel-vectorized: 8 channels/pixel as two float4 (lo/hi). tileA ping-pong
// -> 2 block barriers per 8-channel chunk. Dynamic smem 96KB.

extern __shared__ float4 smem4[];
// tileA: float4[2][4][256][2]  -> 4096 float4 (64KB)
// tileR: float4[4][256][2]     -> 2048 float4 (32KB), base offset 4096

__global__ __launch_bounds__(256, 2)
void fuse_kernel(const float* __restrict__ feat,
                 const float* __restrict__ trans,
                 const int* __restrict__ nag,
                 float* __restrict__ out)
{
    float4* __restrict__ tileA = smem4;
    float4* __restrict__ tileR = smem4 + 4096;

    const int b  = blockIdx.z;
    const int i  = blockIdx.y;
    const int c0 = blockIdx.x * CCHUNK;
    const int t  = threadIdx.x;
    const int x  = t & 15;
    const int y  = t >> 4;

    const int n = nag[b * A_];            // num_agent_tensor[b, 0]
    const bool active = (i < n) && (n > 1);

    const unsigned base = ((unsigned)(i * B_ + b) * C_ + c0) * HW_;
    const float* __restrict__ local = feat + base;
    float* __restrict__ outp        = out  + base;

    // normalized pixel coords (align_corners=False)
    const float xs = (2.f * (float)x + 1.f) / 16.f - 1.f;
    const float ys = (2.f * (float)y + 1.f) / 16.f - 1.f;

    // Per-neighbor tap metadata (channel-invariant).
    float    wA[4][4], wB[4][4];
    unsigned pA[4], pB[4];                // 4 byte-indices packed per table
    unsigned off[4];                      // neighbor block element offset
    bool valid[4];

    #pragma unroll
    for (int jj = 0; jj < 4; jj++) {
        const int j = jj + (jj >= i ? 1 : 0);          // skip j == i
        const bool v = active && (j < n);
        valid[jj] = v;
        off[jj]   = ((unsigned)(j * B_ + b) * C_ + c0) * HW_;
        pA[jj] = 0u; pB[jj] = 0u;
        #pragma unroll
        for (int m = 0; m < 4; m++) { wA[jj][m] = 0.f; wB[jj][m] = 0.f; }
        if (v) {
            const float* T = trans + (((b * A_ + i) * A_ + j) * 16);
            const float t00 = T[0], t01 = T[1], t03 = T[3];
            const float t10 = T[4], t11 = T[5], t13 = T[7];

            // ---- stage 1: rotation grid ----
            const float gx = t00 * xs + t01 * ys;
            const float gy = t10 * xs + t11 * ys;
            const float ix = ((gx + 1.f) * 16.f - 1.f) * 0.5f;
            const float iy = ((gy + 1.f) * 16.f - 1.f) * 0.5f;
            const float x0f = floorf(ix), y0f = floorf(iy);
            const float fx = ix - x0f,  fy = iy - y0f;
            const int x0 = (int)x0f, y0 = (int)y0f;
            #pragma unroll
            for (int m = 0; m < 4; m++) {
                const int dx = m & 1, dy = m >> 1;
                const int xi = x0 + dx, yi = y0 + dy;
                const float w = (dx ? fx : 1.f - fx) * (dy ? fy : 1.f - fy);
                const bool in = (xi >= 0) & (xi < 16) & (yi >= 0) & (yi < 16);
                wA[jj][m] = in ? w : 0.f;
                pA[jj]  |= (unsigned)(in ? (yi * 16 + xi) : 0) << (8 * m);
            }

            // ---- stage 2: translation grid ----
            const float xt = t03 * (1.f / 32.f);      // 4*T03/128
            const float yt = -t13 * (1.f / 32.f);
            const float ix2 = ((xs + xt + 1.f) * 16.f - 1.f) * 0.5f;
            const float iy2 = ((ys + yt + 1.f) * 16.f - 1.f) * 0.5f;
            const float x20f = floorf(ix2), y20f = floorf(iy2);
            const float fx2 = ix2 - x20f,  fy2 = iy2 - y20f;
            const int x20 = (int)x20f, y20 = (int)y20f;
            #pragma unroll
            for (int m = 0; m < 4; m++) {
                const int dx = m & 1, dy = m >> 1;
                const int xi = x20 + dx, yi = y20 + dy;
                const float w = (dx ? fx2 : 1.f - fx2) * (dy ? fy2 : 1.f - fy2);
                const bool in = (xi >= 0) & (xi < 16) & (yi >= 0) & (yi < 16);
                wB[jj][m] = in ? w : 0.f;
                pB[jj]  |= (unsigned)(in ? (yi * 16 + xi) : 0) << (8 * m);
            }
        }
    }

    int p = 0;
    for (int g = 0; g < CCHUNK; g += NC, p ^= 1) {
        // fill buffer p for this chunk (LDG -> STS.128 x2 per neighbor)
        #pragma unroll
        for (int jj = 0; jj < 4; jj++) {
            if (valid[jj]) {                       // uniform across block
                const float* src = feat + off[jj] + (unsigned)g * HW_;
                float4 lo, hi;
                lo.x = src[t];
                lo.y = src[HW_ + t];
                lo.z = src[2 * HW_ + t];
                lo.w = src[3 * HW_ + t];
                hi.x = src[4 * HW_ + t];
                hi.y = src[5 * HW_ + t];
                hi.z = src[6 * HW_ + t];
                hi.w = src[7 * HW_ + t];
                const int bse = ((p * 4 + jj) * 256 + t) * 2;
                tileA[bse]     = lo;
                tileA[bse + 1] = hi;
            }
        }

        float4 aLo, aHi;
        aLo.x = local[(g + 0) * HW_ + t];
        aLo.y = local[(g + 1) * HW_ + t];
        aLo.z = local[(g + 2) * HW_ + t];
        aLo.w = local[(g + 3) * HW_ + t];
        aHi.x = local[(g + 4) * HW_ + t];
        aHi.y = local[(g + 5) * HW_ + t];
        aHi.z = local[(g + 6) * HW_ + t];
        aHi.w = local[(g + 7) * HW_ + t];

        __syncthreads();                  // (a) tileA[p] visible; tileR WAR done

        // stage 1: rotation sample -> R tiles (2 LDS.128 per tap = 8 channels)
        #pragma unroll
        for (int jj = 0; jj < 4; jj++) {
            if (valid[jj]) {
                float4 rLo = make_float4(0.f, 0.f, 0.f, 0.f);
                float4 rHi = make_float4(0.f, 0.f, 0.f, 0.f);
                const int tb = (p * 4 + jj) * 256;
                #pragma unroll
                for (int m = 0; m < 4; m++) {
                    const int idx = (pA[jj] >> (8 * m)) & 255;
                    const float w = wA[jj][m];
                    const float4 vLo = tileA[(tb + idx) * 2];
                    const float4 vHi = tileA[(tb + idx) * 2 + 1];
                    rLo.x += w * vLo.x; rLo.y += w * vLo.y;
                    rLo.z += w * vLo.z; rLo.w += w * vLo.w;
                    rHi.x += w * vHi.x; rHi.y += w * vHi.y;
                    rHi.z += w * vHi.z; rHi.w += w * vHi.w;
                }
                const int rb = (jj * 256 + t) * 2;
                tileR[rb]     = rLo;
                tileR[rb + 1] = rHi;
            }
        }
        __syncthreads();                  // (b) tileR ready

        // stage 2: translation sample -> accumulate
        #pragma unroll
        for (int jj = 0; jj < 4; jj++) {
            if (valid[jj]) {
                const int rb = jj * 256;
                #pragma unroll
                for (int m = 0; m < 4; m++) {
                    const int idx = (pB[jj] >> (8 * m)) & 255;
                    const float w = wB[jj][m];
                    const float4 vLo = tileR[(rb + idx) * 2];
                    const float4 vHi = tileR[(rb + idx) * 2 + 1];
                    aLo.x += w * vLo.x; aLo.y += w * vLo.y;
                    aLo.z += w * vLo.z; aLo.w += w * vLo.w;
                    aHi.x += w * vHi.x; aHi.y += w * vHi.y;
                    aHi.z += w * vHi.z; aHi.w += w * vHi.w;
                }
            }
        }

        outp[(g + 0) * HW_ + t] = aLo.x;
        outp[(g + 1) * HW_ + t] = aLo.y;
        outp[(g + 2) * HW_ + t] = aLo.z;
        outp[(g + 3) * HW_ + t] = aLo.w;
        outp[(g + 4) * HW_ + t] = aHi.x;
        outp[(g + 5) * HW_ + t] = aHi.y;
        outp[(g + 6) * HW_ + t] = aHi.z;
        outp[(g + 7) * HW_ + t] = aHi.w;
    }
}

extern "C" void kernel_launch(void* const* d_in, const int* in_sizes, int n_in,
                              void* d_out, int out_size)
{
    const float* feat  = (const float*)d_in[0];   // [A*B, C, H, W] f32
    const float* trans = (const float*)d_in[1];   // [B, A, A, 4, 4] f32
    const int*   nag   = (const int*)d_in[2];     // [B, A] int32
    float* out = (float*)d_out;                   // [A*B, C, H, W] f32

    static int attr_set = 0;
    if (!attr_set) {
        cudaFuncSetAttribute(fuse_kernel,
                             cudaFuncAttributeMaxDynamicSharedMemorySize, SMEM_BYTES);
        attr_set = 1;
    }

    dim3 grid(C_ / CCHUNK, A_, B_);
    fuse_kernel<<<grid, 256, SMEM_BYTES>>>(feat, trans, nag, out);
}

// round 10
// speedup vs baseline: 1.9695x; 1.6524x over previous
#include <cuda_runtime.h>

#define B_ 16
#define A_ 5
#define C_ 512
#define HW_ 256
#define NC 4
#define CCHUNK 32

// out[(i*B+b)] = local[(i*B+b)] + sum_{j != i, j<n, i<n} warp(local[(j*B+b)], trans[b,i,j])
// warp = bilinear grid_sample chained twice (rotation, then constant translation),
// zero pad, align_corners=False. Geometry channel-invariant -> register tap tables.
// Tiles channel-vectorized float4; tileA ping-pong (2 barriers/chunk); next chunk's
// global loads prefetched into registers during current chunk's compute.
// NOTE: natural register budget (no occupancy-3 cap) — R7 showed capping spills.

__global__ __launch_bounds__(256, 2)
void fuse_kernel(const float* __restrict__ feat,
                 const float* __restrict__ trans,
                 const int* __restrict__ nag,
                 float* __restrict__ out)
{
    __shared__ float4 tileA[2][4][256];   // ping-pong source tiles (4 ch/pixel)
    __shared__ float4 tileR[4][256];      // rotation-sampled intermediates

    const int b  = blockIdx.z;
    const int i  = blockIdx.y;
    const int c0 = blockIdx.x * CCHUNK;
    const int t  = threadIdx.x;
    const int x  = t & 15;
    const int y  = t >> 4;

    const int n = nag[b * A_];            // num_agent_tensor[b, 0]
    const bool active = (i < n) && (n > 1);

    const unsigned base = ((unsigned)(i * B_ + b) * C_ + c0) * HW_;
    const float* __restrict__ local = feat + base;
    float* __restrict__ outp        = out  + base;

    // normalized pixel coords (align_corners=False)
    const float xs = (2.f * (float)x + 1.f) / 16.f - 1.f;
    const float ys = (2.f * (float)y + 1.f) / 16.f - 1.f;

    // Per-neighbor tap metadata (channel-invariant).
    float    wA[4][4], wB[4][4];
    unsigned pA[4], pB[4];                // 4 byte-indices packed per table
    unsigned off[4];                      // neighbor block element offset
    bool valid[4];

    #pragma unroll
    for (int jj = 0; jj < 4; jj++) {
        const int j = jj + (jj >= i ? 1 : 0);          // skip j == i
        const bool v = active && (j < n);
        valid[jj] = v;
        off[jj]   = ((unsigned)(j * B_ + b) * C_ + c0) * HW_;
        pA[jj] = 0u; pB[jj] = 0u;
        #pragma unroll
        for (int m = 0; m < 4; m++) { wA[jj][m] = 0.f; wB[jj][m] = 0.f; }
        if (v) {
            const float* T = trans + (((b * A_ + i) * A_ + j) * 16);
            const float t00 = T[0], t01 = T[1], t03 = T[3];
            const float t10 = T[4], t11 = T[5], t13 = T[7];

            // ---- stage 1: rotation grid ----
            const float gx = t00 * xs + t01 * ys;
            const float gy = t10 * xs + t11 * ys;
            const float ix = ((gx + 1.f) * 16.f - 1.f) * 0.5f;
            const float iy = ((gy + 1.f) * 16.f - 1.f) * 0.5f;
            const float x0f = floorf(ix), y0f = floorf(iy);
            const float fx = ix - x0f,  fy = iy - y0f;
            const int x0 = (int)x0f, y0 = (int)y0f;
            #pragma unroll
            for (int m = 0; m < 4; m++) {
                const int dx = m & 1, dy = m >> 1;
                const int xi = x0 + dx, yi = y0 + dy;
                const float w = (dx ? fx : 1.f - fx) * (dy ? fy : 1.f - fy);
                const bool in = (xi >= 0) & (xi < 16) & (yi >= 0) & (yi < 16);
                wA[jj][m] = in ? w : 0.f;
                pA[jj]  |= (unsigned)(in ? (yi * 16 + xi) : 0) << (8 * m);
            }

            // ---- stage 2: translation grid ----
            const float xt = t03 * (1.f / 32.f);      // 4*T03/128
            const float yt = -t13 * (1.f / 32.f);
            const float ix2 = ((xs + xt + 1.f) * 16.f - 1.f) * 0.5f;
            const float iy2 = ((ys + yt + 1.f) * 16.f - 1.f) * 0.5f;
            const float x20f = floorf(ix2), y20f = floorf(iy2);
            const float fx2 = ix2 - x20f,  fy2 = iy2 - y20f;
            const int x20 = (int)x20f, y20 = (int)y20f;
            #pragma unroll
            for (int m = 0; m < 4; m++) {
                const int dx = m & 1, dy = m >> 1;
                const int xi = x20 + dx, yi = y20 + dy;
                const float w = (dx ? fx2 : 1.f - fx2) * (dy ? fy2 : 1.f - fy2);
                const bool in = (xi >= 0) & (xi < 16) & (yi >= 0) & (yi < 16);
                wB[jj][m] = in ? w : 0.f;
                pB[jj]  |= (unsigned)(in ? (yi * 16 + xi) : 0) << (8 * m);
            }
        }
    }

    // ---- prologue: prefetch chunk 0 fills into registers ----
    float4 pre[4];
    #pragma unroll
    for (int jj = 0; jj < 4; jj++) {
        if (valid[jj]) {
            const float* src = feat + off[jj];
            pre[jj].x = src[t];
            pre[jj].y = src[HW_ + t];
            pre[jj].z = src[2 * HW_ + t];
            pre[jj].w = src[3 * HW_ + t];
        }
    }

    int p = 0;
    for (int g = 0; g < CCHUNK; g += NC, p ^= 1) {
        // deposit prefetched fills (STS.128, conflict-free)
        #pragma unroll
        for (int jj = 0; jj < 4; jj++) {
            if (valid[jj]) tileA[p][jj][t] = pre[jj];
        }

        float4 acc;
        acc.x = local[(g + 0) * HW_ + t];
        acc.y = local[(g + 1) * HW_ + t];
        acc.z = local[(g + 2) * HW_ + t];
        acc.w = local[(g + 3) * HW_ + t];

        __syncthreads();                  // (a) tileA[p] visible; tileR WAR done

        // prefetch next chunk (latency hidden by stage1+stage2 below)
        if (g + NC < CCHUNK) {
            #pragma unroll
            for (int jj = 0; jj < 4; jj++) {
                if (valid[jj]) {
                    const float* src = feat + off[jj] + (unsigned)(g + NC) * HW_;
                    pre[jj].x = src[t];
                    pre[jj].y = src[HW_ + t];
                    pre[jj].z = src[2 * HW_ + t];
                    pre[jj].w = src[3 * HW_ + t];
                }
            }
        }

        // stage 1: rotation sample -> R tiles (one LDS.128 per tap, 4 channels)
        #pragma unroll
        for (int jj = 0; jj < 4; jj++) {
            if (valid[jj]) {
                const float4 v0 = tileA[p][jj][(pA[jj]      ) & 255];
                const float4 v1 = tileA[p][jj][(pA[jj] >>  8) & 255];
                const float4 v2 = tileA[p][jj][(pA[jj] >> 16) & 255];
                const float4 v3 = tileA[p][jj][(pA[jj] >> 24) & 255];
                const float w0 = wA[jj][0], w1 = wA[jj][1], w2 = wA[jj][2], w3 = wA[jj][3];
                float4 r;
                r.x = w0 * v0.x + w1 * v1.x + w2 * v2.x + w3 * v3.x;
                r.y = w0 * v0.y + w1 * v1.y + w2 * v2.y + w3 * v3.y;
                r.z = w0 * v0.z + w1 * v1.z + w2 * v2.z + w3 * v3.z;
                r.w = w0 * v0.w + w1 * v1.w + w2 * v2.w + w3 * v3.w;
                tileR[jj][t] = r;
            }
        }
        __syncthreads();                  // (b) tileR ready

        // stage 2: translation sample -> accumulate
        #pragma unroll
        for (int jj = 0; jj < 4; jj++) {
            if (valid[jj]) {
                const float4 v0 = tileR[jj][(pB[jj]      ) & 255];
                const float4 v1 = tileR[jj][(pB[jj] >>  8) & 255];
                const float4 v2 = tileR[jj][(pB[jj] >> 16) & 255];
                const float4 v3 = tileR[jj][(pB[jj] >> 24) & 255];
                const float w0 = wB[jj][0], w1 = wB[jj][1], w2 = wB[jj][2], w3 = wB[jj][3];
                acc.x += w0 * v0.x + w1 * v1.x + w2 * v2.x + w3 * v3.x;
                acc.y += w0 * v0.y + w1 * v1.y + w2 * v2.y + w3 * v3.y;
                acc.z += w0 * v0.z + w1 * v1.z + w2 * v2.z + w3 * v3.z;
                acc.w += w0 * v0.w + w1 * v1.w + w2 * v2.w + w3 * v3.w;
            }
        }

        outp[(g + 0) * HW_ + t] = acc.x;
        outp[(g + 1) * HW_ + t] = acc.y;
        outp[(g + 2) * HW_ + t] = acc.z;
        outp[(g + 3) * HW_ + t] = acc.w;
    }
}

extern "C" void kernel_launch(void* const* d_in, const int* in_sizes, int n_in,
                              void* d_out, int out_size)
{
    const float* feat  = (const float*)d_in[0];   // [A*B, C, H, W] f32
    const float* trans = (const float*)d_in[1];   // [B, A, A, 4, 4] f32
    const int*   nag   = (const int*)d_in[2];     // [B, A] int32
    float* out = (float*)d_out;                   // [A*B, C, H, W] f32

    dim3 grid(C_ / CCHUNK, A_, B_);
    fuse_kernel<<<grid, 256>>>(feat, trans, nag, out);
}